// round 1
// baseline (speedup 1.0000x reference)
#include <cuda_runtime.h>

// Problem constants (fixed shapes per reference)
#define IN_F     256
#define OUT_F    256
#define BATCH    512
#define NSEG     16
#define NT       49            // (N-1)*SEGMENTS + 1
#define KDIM     (IN_F * NT)   // 12544

#define I_SPLIT  32
#define I_PER    (IN_F / I_SPLIT)   // 8
#define B_TILE   64
#define B_SUB    16                 // per thread (4 b-lanes * 16 = 64)

// Static device scratch (no allocations allowed)
__device__ float  g_wt[KDIM * OUT_F];                 // transposed weights [k][o], 12.85 MB
__device__ float4 g_basis[BATCH * IN_F];              // Lagrange basis, 2 MB
__device__ int    g_wid[BATCH * IN_F];                // 3*segment, 0.5 MB
__device__ float  g_part[I_SPLIT * BATCH * OUT_F];    // split-K partials, 16 MB

// ---------------------------------------------------------------------------
// Kernel 1: tiled 2D transpose  w[o][k] -> wt[k][o]   (k = i*49 + t)
// ---------------------------------------------------------------------------
__global__ void transpose_w_kernel(const float* __restrict__ w) {
    __shared__ float tile[32][33];
    const int k0 = blockIdx.x * 32;
    const int o0 = blockIdx.y * 32;
    const int tx = threadIdx.x;          // 0..31 (k within tile on read)
    const int ty = threadIdx.y;          // 0..7

#pragma unroll
    for (int r = 0; r < 32; r += 8) {
        // read coalesced along k
        tile[ty + r][tx] = w[(size_t)(o0 + ty + r) * KDIM + (k0 + tx)];
    }
    __syncthreads();
#pragma unroll
    for (int r = 0; r < 32; r += 8) {
        // write coalesced along o
        g_wt[(size_t)(k0 + ty + r) * OUT_F + (o0 + tx)] = tile[tx][ty + r];
    }
}

// ---------------------------------------------------------------------------
// Kernel 2: per-(b,i) segment + Lagrange basis (Chebyshev-Lobatto n=4 nodes:
// [-1, -0.5, 0.5, 1])
// ---------------------------------------------------------------------------
__global__ void basis_kernel(const float* __restrict__ x) {
    int idx = blockIdx.x * blockDim.x + threadIdx.x;
    if (idx >= BATCH * IN_F) return;

    float xv = x[idx];
    int s = (int)((xv + 1.0f) * 0.5f * (float)NSEG);
    s = min(max(s, 0), NSEG - 1);

    float xmin = (float)s * (2.0f / (float)NSEG) - 1.0f;
    float xi   = (xv - xmin) * (float)NSEG - 1.0f;   // in [-1, 1]

    float d0 = xi + 1.0f;
    float d1 = xi + 0.5f;
    float d2 = xi - 0.5f;
    float d3 = xi - 1.0f;

    float4 b;
    b.x = d1 * d2 * d3 * (-1.0f / 1.5f);   // j=0, den = -1.5
    b.y = d0 * d2 * d3 * ( 1.0f / 0.75f);  // j=1, den =  0.75
    b.z = d0 * d1 * d3 * (-1.0f / 0.75f);  // j=2, den = -0.75
    b.w = d0 * d1 * d2 * ( 1.0f / 1.5f);   // j=3, den =  1.5

    g_basis[idx] = b;
    g_wid[idx]   = 3 * s;
}

// ---------------------------------------------------------------------------
// Kernel 3: main contraction. Grid: (BATCH/B_TILE = 8, I_SPLIT = 32).
// Block: 256 threads = 64 o-quad threads x 4 b-lanes.
// Each thread: 16 b's x 4 consecutive o's, 8 i's. All loads coalesced/broadcast.
// ---------------------------------------------------------------------------
__global__ __launch_bounds__(256) void pp_main_kernel() {
    const int tid   = threadIdx.x;
    const int oq    = tid & 63;          // o-quad index: o = 4*oq
    const int blane = tid >> 6;          // 0..3 (uniform per warp)
    const int b0    = blockIdx.x * B_TILE + blane * B_SUB;
    const int o     = oq * 4;
    const int i0    = blockIdx.y * I_PER;

    float4 acc[B_SUB];
#pragma unroll
    for (int bb = 0; bb < B_SUB; bb++) acc[bb] = make_float4(0.f, 0.f, 0.f, 0.f);

    for (int ii = 0; ii < I_PER; ii++) {
        const int i = i0 + ii;
        const float* wt_i = g_wt + (size_t)i * (NT * OUT_F) + o;

#pragma unroll 4
        for (int bb = 0; bb < B_SUB; bb++) {
            const int bi = (b0 + bb) * IN_F + i;
            const float4 bas = __ldg(&g_basis[bi]);
            const int    wid = __ldg(&g_wid[bi]);

            const float4* p = (const float4*)(wt_i + (size_t)wid * OUT_F);
            // row stride OUT_F floats = 64 float4s
            float4 w0 = __ldg(p + 0 * 64);
            float4 w1 = __ldg(p + 1 * 64);
            float4 w2 = __ldg(p + 2 * 64);
            float4 w3 = __ldg(p + 3 * 64);

            acc[bb].x = fmaf(bas.x, w0.x, fmaf(bas.y, w1.x, fmaf(bas.z, w2.x, fmaf(bas.w, w3.x, acc[bb].x))));
            acc[bb].y = fmaf(bas.x, w0.y, fmaf(bas.y, w1.y, fmaf(bas.z, w2.y, fmaf(bas.w, w3.y, acc[bb].y))));
            acc[bb].z = fmaf(bas.x, w0.z, fmaf(bas.y, w1.z, fmaf(bas.z, w2.z, fmaf(bas.w, w3.z, acc[bb].z))));
            acc[bb].w = fmaf(bas.x, w0.w, fmaf(bas.y, w1.w, fmaf(bas.z, w2.w, fmaf(bas.w, w3.w, acc[bb].w))));
        }
    }

    float* outp = g_part + (size_t)blockIdx.y * (BATCH * OUT_F);
#pragma unroll
    for (int bb = 0; bb < B_SUB; bb++) {
        *(float4*)(outp + (size_t)(b0 + bb) * OUT_F + o) = acc[bb];
    }
}

// ---------------------------------------------------------------------------
// Kernel 4: reduce the 32 i-split partials (deterministic order)
// ---------------------------------------------------------------------------
__global__ void reduce_kernel(float* __restrict__ out) {
    const int idx = blockIdx.x * blockDim.x + threadIdx.x;  // over 32768 float4s
    const float4* p = (const float4*)g_part;
    float4 s = make_float4(0.f, 0.f, 0.f, 0.f);
#pragma unroll
    for (int k = 0; k < I_SPLIT; k++) {
        float4 v = __ldg(p + (size_t)k * (BATCH * OUT_F / 4) + idx);
        s.x += v.x; s.y += v.y; s.z += v.z; s.w += v.w;
    }
    ((float4*)out)[idx] = s;
}

// ---------------------------------------------------------------------------
extern "C" void kernel_launch(void* const* d_in, const int* in_sizes, int n_in,
                              void* d_out, int out_size) {
    const float* x = (const float*)d_in[0];   // [512, 256] f32
    const float* w = (const float*)d_in[1];   // [256, 256, 49] f32
    float* out = (float*)d_out;               // [512, 256] f32
    (void)in_sizes; (void)n_in; (void)out_size;

    // 1) transpose w -> wt[k][o]
    {
        dim3 grid(KDIM / 32, OUT_F / 32);     // (392, 8)
        dim3 block(32, 8);
        transpose_w_kernel<<<grid, block>>>(w);
    }
    // 2) basis + segment ids
    {
        int total = BATCH * IN_F;             // 131072
        basis_kernel<<<total / 256, 256>>>(x);
    }
    // 3) main contraction into split-K partials
    {
        dim3 grid(BATCH / B_TILE, I_SPLIT);   // (8, 32) = 256 CTAs
        pp_main_kernel<<<grid, 256>>>();
    }
    // 4) reduce partials
    {
        int total4 = BATCH * OUT_F / 4;       // 32768
        reduce_kernel<<<total4 / 256, 256>>>(out);
    }
}

// round 2
// speedup vs baseline: 1.6289x; 1.6289x over previous
#include <cuda_runtime.h>

// Problem constants (fixed shapes per reference)
#define IN_F     256
#define OUT_F    256
#define BATCH    512
#define NSEG     16
#define NT       49            // (N-1)*SEGMENTS + 1
#define KDIM     (IN_F * NT)   // 12544

#define I_SPLIT  32
#define I_PER    (IN_F / I_SPLIT)   // 8
#define B_TILE   128
#define B_SUB    16                 // per thread (8 b-lanes * 16 = 128)

// Static device scratch (no allocations allowed)
__device__ float  g_wt[KDIM * OUT_F];                 // transposed weights [k][o], 12.85 MB
__device__ float4 g_basis[BATCH * IN_F];              // Lagrange basis, 2 MB
__device__ int    g_off[BATCH * IN_F];                // wid * OUT_F (float offset)
__device__ float  g_part[I_SPLIT * BATCH * OUT_F];    // split-K partials, 16 MB

// ---------------------------------------------------------------------------
// Kernel 1: tiled 2D transpose  w[o][k] -> wt[k][o]   (k = i*49 + t)
// ---------------------------------------------------------------------------
__global__ void transpose_w_kernel(const float* __restrict__ w) {
    __shared__ float tile[32][33];
    const int k0 = blockIdx.x * 32;
    const int o0 = blockIdx.y * 32;
    const int tx = threadIdx.x;          // 0..31
    const int ty = threadIdx.y;          // 0..7

#pragma unroll
    for (int r = 0; r < 32; r += 8) {
        tile[ty + r][tx] = w[(size_t)(o0 + ty + r) * KDIM + (k0 + tx)];
    }
    __syncthreads();
#pragma unroll
    for (int r = 0; r < 32; r += 8) {
        g_wt[(size_t)(k0 + ty + r) * OUT_F + (o0 + tx)] = tile[tx][ty + r];
    }
}

// ---------------------------------------------------------------------------
// Kernel 2: per-(b,i) segment + Lagrange basis (Chebyshev-Lobatto n=4 nodes:
// [-1, -0.5, 0.5, 1]); also precompute the weight-row offset wid*OUT_F.
// ---------------------------------------------------------------------------
__global__ void basis_kernel(const float* __restrict__ x) {
    int idx = blockIdx.x * blockDim.x + threadIdx.x;
    if (idx >= BATCH * IN_F) return;

    float xv = x[idx];
    int s = (int)((xv + 1.0f) * 0.5f * (float)NSEG);
    s = min(max(s, 0), NSEG - 1);

    float xmin = (float)s * (2.0f / (float)NSEG) - 1.0f;
    float xi   = (xv - xmin) * (float)NSEG - 1.0f;   // in [-1, 1]

    float d0 = xi + 1.0f;
    float d1 = xi + 0.5f;
    float d2 = xi - 0.5f;
    float d3 = xi - 1.0f;

    float4 b;
    b.x = d1 * d2 * d3 * (-1.0f / 1.5f);
    b.y = d0 * d2 * d3 * ( 1.0f / 0.75f);
    b.z = d0 * d1 * d3 * (-1.0f / 0.75f);
    b.w = d0 * d1 * d2 * ( 1.0f / 1.5f);

    g_basis[idx] = b;
    g_off[idx]   = 3 * s * OUT_F;     // row offset in floats
}

// ---------------------------------------------------------------------------
// Kernel 3: main contraction. Grid: (BATCH/B_TILE = 4, I_SPLIT = 32) = 128 CTAs.
// Block: 512 threads = 64 o-quad threads x 8 b-lanes. 1 CTA/SM, 16 warps/SM.
// Each thread: 16 b's x 4 consecutive o's, 8 i's. Accumulators FULLY unrolled
// (compile-time indexed -> stay in registers).
// ---------------------------------------------------------------------------
__global__ __launch_bounds__(512, 1) void pp_main_kernel() {
    __shared__ float4 s_bas[I_PER][B_TILE];
    __shared__ int    s_off[I_PER][B_TILE];

    const int tid   = threadIdx.x;
    const int oq    = tid & 63;          // o = 4*oq
    const int blane = tid >> 6;          // 0..7 (uniform per warp)
    const int bt0   = blockIdx.x * B_TILE;
    const int i0    = blockIdx.y * I_PER;

    // Stage the (basis, offset) tile for this CTA's (b-tile, i-range)
    for (int e = tid; e < I_PER * B_TILE; e += 512) {
        int bl = e >> 3;                 // 0..127
        int il = e & 7;                  // 0..7 (fastest -> coalesced-ish)
        int gi = (bt0 + bl) * IN_F + (i0 + il);
        s_bas[il][bl] = g_basis[gi];
        s_off[il][bl] = g_off[gi];
    }
    __syncthreads();

    float4 acc[B_SUB];
#pragma unroll
    for (int bb = 0; bb < B_SUB; bb++) acc[bb] = make_float4(0.f, 0.f, 0.f, 0.f);

    const int bloc0 = blane * B_SUB;

#pragma unroll 1
    for (int ii = 0; ii < I_PER; ii++) {
        const float* wt_i = g_wt + (size_t)(i0 + ii) * (NT * OUT_F) + oq * 4;

#pragma unroll
        for (int bb = 0; bb < B_SUB; bb++) {
            const float4 bas = s_bas[ii][bloc0 + bb];
            const int    off = s_off[ii][bloc0 + bb];

            const float4* p = (const float4*)(wt_i + off);
            float4 w0 = __ldg(p + 0 * 64);     // rows OUT_F floats apart
            float4 w1 = __ldg(p + 1 * 64);
            float4 w2 = __ldg(p + 2 * 64);
            float4 w3 = __ldg(p + 3 * 64);

            acc[bb].x = fmaf(bas.x, w0.x, fmaf(bas.y, w1.x, fmaf(bas.z, w2.x, fmaf(bas.w, w3.x, acc[bb].x))));
            acc[bb].y = fmaf(bas.x, w0.y, fmaf(bas.y, w1.y, fmaf(bas.z, w2.y, fmaf(bas.w, w3.y, acc[bb].y))));
            acc[bb].z = fmaf(bas.x, w0.z, fmaf(bas.y, w1.z, fmaf(bas.z, w2.z, fmaf(bas.w, w3.z, acc[bb].z))));
            acc[bb].w = fmaf(bas.x, w0.w, fmaf(bas.y, w1.w, fmaf(bas.z, w2.w, fmaf(bas.w, w3.w, acc[bb].w))));
        }
    }

    float* outp = g_part + (size_t)blockIdx.y * (BATCH * OUT_F);
#pragma unroll
    for (int bb = 0; bb < B_SUB; bb++) {
        int b = bt0 + bloc0 + bb;
        *(float4*)(outp + (size_t)b * OUT_F + oq * 4) = acc[bb];
    }
}

// ---------------------------------------------------------------------------
// Kernel 4: reduce the 32 i-split partials. Block = 256 threads =
// 64 outputs x 4 k-groups (8 partials each), combined via smem in fixed order.
// Grid = 512 CTAs -> good occupancy + MLP.
// ---------------------------------------------------------------------------
__global__ __launch_bounds__(256) void reduce_kernel(float* __restrict__ out) {
    __shared__ float4 sm[256];
    const int tid = threadIdx.x;
    const int o4  = blockIdx.x * 64 + (tid & 63);   // float4 index, 0..32767
    const int kg  = tid >> 6;                        // 0..3

    const float4* p = (const float4*)g_part + o4;
    float4 s = make_float4(0.f, 0.f, 0.f, 0.f);
#pragma unroll
    for (int k = 0; k < 8; k++) {
        float4 v = __ldg(p + (size_t)(kg * 8 + k) * (BATCH * OUT_F / 4));
        s.x += v.x; s.y += v.y; s.z += v.z; s.w += v.w;
    }
    sm[tid] = s;
    __syncthreads();

    if (kg == 0) {
        float4 a = sm[tid], b = sm[tid + 64], c = sm[tid + 128], d = sm[tid + 192];
        float4 r;
        r.x = ((a.x + b.x) + c.x) + d.x;
        r.y = ((a.y + b.y) + c.y) + d.y;
        r.z = ((a.z + b.z) + c.z) + d.z;
        r.w = ((a.w + b.w) + c.w) + d.w;
        ((float4*)out)[o4] = r;
    }
}

// ---------------------------------------------------------------------------
extern "C" void kernel_launch(void* const* d_in, const int* in_sizes, int n_in,
                              void* d_out, int out_size) {
    const float* x = (const float*)d_in[0];   // [512, 256] f32
    const float* w = (const float*)d_in[1];   // [256, 256, 49] f32
    float* out = (float*)d_out;               // [512, 256] f32
    (void)in_sizes; (void)n_in; (void)out_size;

    // 1) transpose w -> wt[k][o]
    {
        dim3 grid(KDIM / 32, OUT_F / 32);     // (392, 8)
        dim3 block(32, 8);
        transpose_w_kernel<<<grid, block>>>(w);
    }
    // 2) basis + row offsets
    {
        int total = BATCH * IN_F;             // 131072
        basis_kernel<<<total / 256, 256>>>(x);
    }
    // 3) main contraction into split-K partials
    {
        dim3 grid(BATCH / B_TILE, I_SPLIT);   // (4, 32) = 128 CTAs
        pp_main_kernel<<<grid, 512>>>();
    }
    // 4) reduce partials
    {
        reduce_kernel<<<512, 256>>>(out);
    }
}

// round 4
// speedup vs baseline: 1.6817x; 1.0324x over previous
#include <cuda_runtime.h>

// Problem constants (fixed shapes per reference)
#define IN_F     256
#define OUT_F    256
#define BATCH    512
#define NSEG     16
#define NT       49            // (N-1)*SEGMENTS + 1
#define KDIM     (IN_F * NT)   // 12544

#define I_SPLIT  32
#define I_PER    (IN_F / I_SPLIT)   // 8
#define B_TILE   64
#define B_SUB    16                 // per thread (4 b-lanes * 16 = 64)

// Static device scratch (no allocations allowed)
__device__ float  g_wt[KDIM * OUT_F];                 // transposed weights [k][o], 12.85 MB
__device__ float  g_part[I_SPLIT * BATCH * OUT_F];    // split-K partials, 16 MB

// ---------------------------------------------------------------------------
// Kernel 1: tiled transpose  w[o][k] -> wt[k][o], float4-vectorized global
// reads, SCALAR smem stores (row stride 129 is not 16B-aligned for odd rows).
// Tile: 32 o-rows x 128 k-cols. Grid (98, 8), block (32, 8).
// ---------------------------------------------------------------------------
__global__ __launch_bounds__(256) void transpose_w_kernel(const float* __restrict__ w) {
    __shared__ float tile[32][129];      // odd stride -> conflict-free column reads
    const int k0 = blockIdx.x * 128;
    const int o0 = blockIdx.y * 32;
    const int tx = threadIdx.x;          // 0..31
    const int ty = threadIdx.y;          // 0..7

#pragma unroll
    for (int r = 0; r < 32; r += 8) {
        const int row = ty + r;
        float4 v = *(const float4*)(w + (size_t)(o0 + row) * KDIM + k0 + tx * 4);
        tile[row][tx * 4 + 0] = v.x;     // scalar STS: always aligned
        tile[row][tx * 4 + 1] = v.y;
        tile[row][tx * 4 + 2] = v.z;
        tile[row][tx * 4 + 3] = v.w;
    }
    __syncthreads();

    // write coalesced along o: for each k, 32 consecutive o's
#pragma unroll
    for (int r = 0; r < 16; r++) {
        const int kk = ty + r * 8;       // 0..127
        g_wt[(size_t)(k0 + kk) * OUT_F + (o0 + tx)] = tile[tx][kk];
    }
}

// ---------------------------------------------------------------------------
// Kernel 2 (main): fused basis + gather-contraction.
// Grid: (BATCH/B_TILE = 8, I_SPLIT = 32) = 256 CTAs. Block: 256 threads =
// 64 o-quads x 4 b-lanes; 2 CTAs/SM. Each thread: 16 b x 4 o x 8 i.
// Chebyshev-Lobatto n=4 nodes: [-1, -0.5, 0.5, 1].
// ---------------------------------------------------------------------------
__global__ __launch_bounds__(256, 2) void pp_main_kernel(const float* __restrict__ x) {
    __shared__ float4 s_bas[I_PER][B_TILE];
    __shared__ int    s_off[I_PER][B_TILE];

    const int tid   = threadIdx.x;
    const int oq    = tid & 63;          // o = 4*oq
    const int blane = tid >> 6;          // 0..3 (uniform per warp)
    const int bt0   = blockIdx.x * B_TILE;
    const int i0    = blockIdx.y * I_PER;

    // Compute basis + weight-row offsets for this CTA's (b-tile, i-range).
#pragma unroll
    for (int e = tid; e < I_PER * B_TILE; e += 256) {
        const int bl = e >> 3;           // 0..63
        const int il = e & 7;            // 0..7
        const float xv = x[(bt0 + bl) * IN_F + (i0 + il)];

        int s = (int)((xv + 1.0f) * 0.5f * (float)NSEG);
        s = min(max(s, 0), NSEG - 1);
        const float xmin = (float)s * (2.0f / (float)NSEG) - 1.0f;
        const float xi   = (xv - xmin) * (float)NSEG - 1.0f;

        const float d0 = xi + 1.0f;
        const float d1 = xi + 0.5f;
        const float d2 = xi - 0.5f;
        const float d3 = xi - 1.0f;

        float4 b;
        b.x = d1 * d2 * d3 * (-1.0f / 1.5f);
        b.y = d0 * d2 * d3 * ( 1.0f / 0.75f);
        b.z = d0 * d1 * d3 * (-1.0f / 0.75f);
        b.w = d0 * d1 * d2 * ( 1.0f / 1.5f);

        s_bas[il][bl] = b;
        s_off[il][bl] = 3 * s * OUT_F;
    }
    __syncthreads();

    float4 acc[B_SUB];
#pragma unroll
    for (int bb = 0; bb < B_SUB; bb++) acc[bb] = make_float4(0.f, 0.f, 0.f, 0.f);

    const int bloc0 = blane * B_SUB;

#pragma unroll 1
    for (int ii = 0; ii < I_PER; ii++) {
        const float* wt_i = g_wt + (size_t)(i0 + ii) * (NT * OUT_F) + oq * 4;

#pragma unroll
        for (int bb = 0; bb < B_SUB; bb++) {
            const float4 bas = s_bas[ii][bloc0 + bb];   // warp-uniform broadcast
            const int    off = s_off[ii][bloc0 + bb];

            const float4* p = (const float4*)(wt_i + off);
            float4 w0 = __ldg(p + 0 * 64);     // rows OUT_F floats = 64 float4s apart
            float4 w1 = __ldg(p + 1 * 64);
            float4 w2 = __ldg(p + 2 * 64);
            float4 w3 = __ldg(p + 3 * 64);

            acc[bb].x = fmaf(bas.x, w0.x, fmaf(bas.y, w1.x, fmaf(bas.z, w2.x, fmaf(bas.w, w3.x, acc[bb].x))));
            acc[bb].y = fmaf(bas.x, w0.y, fmaf(bas.y, w1.y, fmaf(bas.z, w2.y, fmaf(bas.w, w3.y, acc[bb].y))));
            acc[bb].z = fmaf(bas.x, w0.z, fmaf(bas.y, w1.z, fmaf(bas.z, w2.z, fmaf(bas.w, w3.z, acc[bb].z))));
            acc[bb].w = fmaf(bas.x, w0.w, fmaf(bas.y, w1.w, fmaf(bas.z, w2.w, fmaf(bas.w, w3.w, acc[bb].w))));
        }
    }

    float* outp = g_part + (size_t)blockIdx.y * (BATCH * OUT_F);
#pragma unroll
    for (int bb = 0; bb < B_SUB; bb++) {
        const int b = bt0 + bloc0 + bb;
        *(float4*)(outp + (size_t)b * OUT_F + oq * 4) = acc[bb];
    }
}

// ---------------------------------------------------------------------------
// Kernel 3: reduce the 32 i-split partials. Block = 512 threads =
// 64 outputs x 8 k-groups (4 partials each); smem tree in fixed order.
// Grid = 512 CTAs -> 262K threads, high occupancy + MLP 4/thread.
// ---------------------------------------------------------------------------
__global__ __launch_bounds__(512) void reduce_kernel(float* __restrict__ out) {
    __shared__ float4 sm[512];
    const int tid = threadIdx.x;
    const int o4  = blockIdx.x * 64 + (tid & 63);   // float4 index, 0..32767
    const int kg  = tid >> 6;                        // 0..7

    const float4* p = (const float4*)g_part + o4;
    float4 s = make_float4(0.f, 0.f, 0.f, 0.f);
#pragma unroll
    for (int k = 0; k < 4; k++) {
        float4 v = __ldg(p + (size_t)(kg * 4 + k) * (BATCH * OUT_F / 4));
        s.x += v.x; s.y += v.y; s.z += v.z; s.w += v.w;
    }
    sm[tid] = s;
    __syncthreads();

    if (kg < 2) {
        float4 a = sm[tid], b = sm[tid + 128], c = sm[tid + 256], d = sm[tid + 384];
        float4 r;
        r.x = ((a.x + b.x) + c.x) + d.x;
        r.y = ((a.y + b.y) + c.y) + d.y;
        r.z = ((a.z + b.z) + c.z) + d.z;
        r.w = ((a.w + b.w) + c.w) + d.w;
        sm[tid] = r;
    }
    __syncthreads();
    if (kg == 0) {
        float4 a = sm[tid], b = sm[tid + 64];
        float4 r;
        r.x = a.x + b.x; r.y = a.y + b.y; r.z = a.z + b.z; r.w = a.w + b.w;
        ((float4*)out)[o4] = r;
    }
}

// ---------------------------------------------------------------------------
extern "C" void kernel_launch(void* const* d_in, const int* in_sizes, int n_in,
                              void* d_out, int out_size) {
    const float* x = (const float*)d_in[0];   // [512, 256] f32
    const float* w = (const float*)d_in[1];   // [256, 256, 49] f32
    float* out = (float*)d_out;               // [512, 256] f32
    (void)in_sizes; (void)n_in; (void)out_size;

    // 1) transpose w -> wt[k][o]
    {
        dim3 grid(KDIM / 128, OUT_F / 32);    // (98, 8)
        dim3 block(32, 8);
        transpose_w_kernel<<<grid, block>>>(w);
    }
    // 2) main contraction (fused basis) into split-K partials
    {
        dim3 grid(BATCH / B_TILE, I_SPLIT);   // (8, 32) = 256 CTAs
        pp_main_kernel<<<grid, 256>>>(x);
    }
    // 3) reduce partials
    {
        reduce_kernel<<<512, 512>>>(out);
    }
}